// round 8
// baseline (speedup 1.0000x reference)
#include <cuda_runtime.h>
#include <cuda_bf16.h>
#include <cstdint>
#include <math.h>

// ===================== constants =====================
static constexpr int DIMK = 128;

// smem layout (bytes), dynamic. fp8 tiles: 128 rows x 128 B, stride 144.
static constexpr int TS      = 144;                 // padded row stride (bytes)
static constexpr int TILE_B  = 128 * TS;            // 18432
static constexpr int SM_A    = 0;                   // A tile; overlaid by RED at end
static constexpr int SM_B0   = TILE_B;              // 18432
static constexpr int SM_B1   = 2 * TILE_B;          // 36864
static constexpr int SM_CA   = 3 * TILE_B;          // 55296, 2 slots x 1KB (float2[128])
static constexpr int SM_NORM = SM_CA + 2048;        // 57344, 128 floats
static constexpr int SMEM_TOTAL = SM_NORM + 512;    // 57856

// ===================== scratch (no cudaMalloc) =====================
__device__ uint8_t g_Cb[2048 * DIMK];   // e4m3 scaled centers
__device__ float2  g_c2a[2048];         // (-0.5*||c'||^2 , alpha)
__device__ float   g_predsMM[2048];
__device__ float   g_partials[1024];
__device__ float   g_preds_fallback[100352];

// ===================== PTX helpers =====================
__device__ __forceinline__ uint32_t smem_u32(const void* p) {
    uint32_t a;
    asm("{ .reg .u64 t; cvta.to.shared.u64 t, %1; cvt.u32.u64 %0, t; }" : "=r"(a) : "l"(p));
    return a;
}
__device__ __forceinline__ void cpa16(uint32_t dst, const void* src) {
    asm volatile("cp.async.cg.shared.global [%0], [%1], 16;" :: "r"(dst), "l"(src));
}
#define CP_COMMIT() asm volatile("cp.async.commit_group;" ::: "memory")
#define CP_WAIT0()  asm volatile("cp.async.wait_group 0;"  ::: "memory")

__device__ __forceinline__ void ldmx4(uint32_t* r, uint32_t addr) {
    asm volatile("ldmatrix.sync.aligned.m8n8.x4.shared.b16 {%0,%1,%2,%3}, [%4];"
                 : "=r"(r[0]), "=r"(r[1]), "=r"(r[2]), "=r"(r[3]) : "r"(addr));
}
// fp8 e4m3 mma: m16n8k32, f32 accumulate
__device__ __forceinline__ void mma_fp8(float* c, const uint32_t* a,
                                        uint32_t b0, uint32_t b1) {
    asm volatile("mma.sync.aligned.m16n8k32.row.col.f32.e4m3.e4m3.f32 "
                 "{%0,%1,%2,%3}, {%4,%5,%6,%7}, {%8,%9}, {%0,%1,%2,%3};"
                 : "+f"(c[0]), "+f"(c[1]), "+f"(c[2]), "+f"(c[3])
                 : "r"(a[0]), "r"(a[1]), "r"(a[2]), "r"(a[3]), "r"(b0), "r"(b1));
}
__device__ __forceinline__ float ex2f(float x) {
    float y; asm("ex2.approx.ftz.f32 %0, %1;" : "=f"(y) : "f"(x)); return y;
}
// q = sqrt(log2e)/sigma so that (q a)·(q b) = log2e * (a.b)/sigma^2
__device__ __forceinline__ float qscale(float sg) {
    return sqrtf(1.44269504088896340736f) / sg;
}
// pack 4 floats -> 4 e4m3 (one uint32), low element first
__device__ __forceinline__ uint32_t pack_fp8x4(float x, float y, float z, float w) {
    uint16_t lo, hi;
    asm("cvt.rn.satfinite.e4m3x2.f32 %0, %1, %2;" : "=h"(lo) : "f"(y), "f"(x));
    asm("cvt.rn.satfinite.e4m3x2.f32 %0, %1, %2;" : "=h"(hi) : "f"(w), "f"(z));
    return (uint32_t)lo | ((uint32_t)hi << 16);
}
// unpack 2 e4m3 (uint16) -> float2, for rounded-norm computation
__device__ __forceinline__ float2 unpack_fp8x2(uint16_t v) {
    uint32_t h2;
    asm("cvt.rn.f16x2.e4m3x2 %0, %1;" : "=r"(h2) : "h"(v));
    __half2 hh = *(__half2*)&h2;
    return __half22float2(hh);
}
__device__ __forceinline__ float norm_accum_u32(uint32_t w, float nrm) {
    float2 f0 = unpack_fp8x2((uint16_t)(w & 0xFFFF));
    float2 f1 = unpack_fp8x2((uint16_t)(w >> 16));
    nrm = fmaf(f0.x, f0.x, nrm); nrm = fmaf(f0.y, f0.y, nrm);
    nrm = fmaf(f1.x, f1.x, nrm); nrm = fmaf(f1.y, f1.y, nrm);
    return nrm;
}

// ===================== centers conv: fp32 -> e4m3 (scaled), (d, alpha) ======
__global__ void convC_kernel(const float* __restrict__ C,
                             uint8_t* __restrict__ Cb,
                             float2* __restrict__ c2a,
                             const float* __restrict__ alpha,
                             const float* __restrict__ sigma_p, int m)
{
    int row  = blockIdx.x * 8 + (threadIdx.x >> 5);
    int lane = threadIdx.x & 31;
    if (row >= m) return;
    const float q = qscale(*sigma_p);
    float4 v = ((const float4*)(C + (size_t)row * DIMK))[lane];
    uint32_t w = pack_fp8x4(q * v.x, q * v.y, q * v.z, q * v.w);
    float nrm = norm_accum_u32(w, 0.f);
    #pragma unroll
    for (int o = 16; o > 0; o >>= 1) nrm += __shfl_xor_sync(0xffffffffu, nrm, o);
    ((uint32_t*)(Cb + (size_t)row * DIMK))[lane] = w;
    if (lane == 0) c2a[row] = make_float2(-0.5f * nrm, alpha[row]);
}

// ===================== B-tile async loader (fp8 128x128B, 128 threads) =====
__device__ __forceinline__ void load_tile_async(uint32_t smBase,
                                                const uint8_t* __restrict__ src,
                                                int tid)
{
    #pragma unroll
    for (int it = 0; it < 8; ++it) {
        int i   = tid + it * 128;
        int row = i >> 3;
        int kb  = i & 7;
        cpa16(smBase + row * TS + kb * 16, src + row * 128 + kb * 16);
    }
}

// ===================== fused RBF matvec + loss partials (FP8 HMMA) ==========
// Blocks [0, nBlocksX): rows of X -> preds, partial = sum (pred-y)^2
// rest: rows of centers -> predsMM,  partial = sum alpha*predMM
__global__ void __launch_bounds__(128, 3)
rbf_hmma_kernel(const float* __restrict__ Xf, const float* __restrict__ Cf,
                const uint8_t* __restrict__ Cb,
                const float2* __restrict__ c2a,
                const float* __restrict__ Y,
                const float* __restrict__ sigma_p,
                float* __restrict__ preds, float* __restrict__ predsMM,
                float* __restrict__ partials,
                int nRows, int nBlocksX, int mCols)
{
    extern __shared__ char smem[];
    const uint32_t sb = smem_u32(smem);
    const int tid   = threadIdx.x;
    const int lane  = tid & 31;
    const int wid   = tid >> 5;
    const int warpM = wid & 1;          // 2 warps over M (64 rows each)
    const int warpN = wid >> 1;         // 2 warps over N (64 cols each)
    const int g     = lane >> 2;
    const int tq    = lane & 3;

    const bool isX = ((int)blockIdx.x < nBlocksX);
    const float* Asrc  = isX ? Xf : Cf;
    const int   srcN   = isX ? nRows : mCols;
    float* outp        = isX ? preds : predsMM;
    const int rowBase  = (isX ? blockIdx.x : blockIdx.x - nBlocksX) * 128;

    const float q = qscale(*sigma_p);

    // ---- prologue: start async C tile 0 + CA slot 0 ----
    load_tile_async(sb + SM_B0, Cb, tid);
    if (tid < 64) cpa16(sb + SM_CA + tid * 16, (const char*)c2a + tid * 16);
    CP_COMMIT();

    // ---- load A tile fp32 -> scaled e4m3 smem (coalesced) ----
    #pragma unroll
    for (int i = 0; i < 32; ++i) {
        int idx = tid + i * 128;            // 4096 float4 chunks
        int r = idx >> 5, c4 = idx & 31;
        int gr = rowBase + r; if (gr >= srcN) gr = srcN - 1;
        float4 v = ((const float4*)(Asrc + (size_t)gr * DIMK))[c4];
        uint32_t w = pack_fp8x4(q * v.x, q * v.y, q * v.z, q * v.w);
        *(uint32_t*)(smem + SM_A + r * TS + c4 * 4) = w;
    }
    __syncthreads();

    // ---- row norms from ROUNDED fp8 (1 thread/row) ----
    {
        float nrm = 0.f;
        #pragma unroll
        for (int j = 0; j < 8; ++j) {
            uint4 v = *(const uint4*)(smem + SM_A + tid * TS + j * 16);
            nrm = norm_accum_u32(v.x, nrm);
            nrm = norm_accum_u32(v.y, nrm);
            nrm = norm_accum_u32(v.z, nrm);
            nrm = norm_accum_u32(v.w, nrm);
        }
        ((float*)(smem + SM_NORM))[tid] = -0.5f * nrm;
    }
    __syncthreads();

    // caR[mf*2+h] = -0.5*||row||^2 for rows warpM*64 + mf*16 + g + h*8
    float caR[8];
    {
        const float* nm = (const float*)(smem + SM_NORM);
        #pragma unroll
        for (int mf = 0; mf < 4; ++mf)
            #pragma unroll
            for (int h = 0; h < 2; ++h)
                caR[mf*2 + h] = nm[warpM*64 + mf*16 + g + h*8];
    }

    // ---- A fragments persist in registers across ALL tiles ----
    // fp8 pairs behave as b16 units: ldmatrix.m8n8.b16 addressing unchanged.
    const int ti = lane >> 3, rr = lane & 7;
    uint32_t aF[4][4][4];               // [mf][ks][4] = 64 regs
    #pragma unroll
    for (int mf = 0; mf < 4; ++mf) {
        uint32_t base = sb + SM_A + (warpM*64 + mf*16 + (ti & 1)*8 + rr) * TS
                        + (ti >> 1) * 16;
        #pragma unroll
        for (int ks = 0; ks < 4; ++ks) ldmx4(aF[mf][ks], base + ks * 32);
    }

    // B ldmatrix offsets (4 slices of 16 cols)
    uint32_t bOff[4];
    #pragma unroll
    for (int p = 0; p < 4; ++p)
        bOff[p] = (uint32_t)((warpN*64 + p*16 + (ti >> 1)*8 + rr) * TS + (ti & 1) * 16);

    float rowAcc[8] = {0.f,0.f,0.f,0.f,0.f,0.f,0.f,0.f};
    const int nT = mCols >> 7;      // 16
    CP_WAIT0();
    __syncthreads();

    for (int t = 0; t < nT; ++t) {
        if (t + 1 < nT) {
            load_tile_async(sb + (((t + 1) & 1) ? SM_B1 : SM_B0),
                            Cb + (size_t)(t + 1) * 128 * DIMK, tid);
            if (tid < 64)
                cpa16(sb + SM_CA + ((t + 1) & 1) * 1024 + tid * 16,
                      (const char*)(c2a + (size_t)(t + 1) * 128) + tid * 16);
            CP_COMMIT();
        }
        const uint32_t bB  = sb + ((t & 1) ? SM_B1 : SM_B0);
        const char*   caP  = smem + SM_CA + (t & 1) * 1024 + (size_t)warpN * 64 * 8;

        // 4 slices of 16 cols: short MMA burst + immediate epilogue (pipe mixing)
        #pragma unroll
        for (int p = 0; p < 4; ++p) {
            float acc[4][2][4];
            #pragma unroll
            for (int mf = 0; mf < 4; ++mf)
                #pragma unroll
                for (int nl = 0; nl < 2; ++nl)
                    #pragma unroll
                    for (int e = 0; e < 4; ++e) acc[mf][nl][e] = 0.f;

            uint32_t rb[2][4];
            ldmx4(rb[0], bB + bOff[p]);
            #pragma unroll
            for (int ks = 0; ks < 4; ++ks) {
                if (ks < 3) ldmx4(rb[(ks + 1) & 1], bB + bOff[p] + (ks + 1) * 32);
                const uint32_t* b = rb[ks & 1];
                #pragma unroll
                for (int mf = 0; mf < 4; ++mf) {
                    mma_fp8(acc[mf][0], aF[mf][ks], b[0], b[1]);
                    mma_fp8(acc[mf][1], aF[mf][ks], b[2], b[3]);
                }
            }
            // epilogue for this 16-col slice
            #pragma unroll
            for (int nl = 0; nl < 2; ++nl) {
                float4 cc = *(const float4*)(caP + ((p*2 + nl)*8 + tq*2) * 8);
                #pragma unroll
                for (int mf = 0; mf < 4; ++mf) {
                    const float* a = acc[mf][nl];
                    float e0 = a[0] + (caR[mf*2]     + cc.x);
                    float e1 = a[1] + (caR[mf*2]     + cc.z);
                    float e2 = a[2] + (caR[mf*2 + 1] + cc.x);
                    float e3 = a[3] + (caR[mf*2 + 1] + cc.z);
                    rowAcc[mf*2]     = fmaf(ex2f(e0), cc.y, rowAcc[mf*2]);
                    rowAcc[mf*2]     = fmaf(ex2f(e1), cc.w, rowAcc[mf*2]);
                    rowAcc[mf*2 + 1] = fmaf(ex2f(e2), cc.y, rowAcc[mf*2 + 1]);
                    rowAcc[mf*2 + 1] = fmaf(ex2f(e3), cc.w, rowAcc[mf*2 + 1]);
                }
            }
        }
        CP_WAIT0();
        __syncthreads();
    }

    // quad reduce (4 threads share each row), then cross-warpN via smem
    #pragma unroll
    for (int i = 0; i < 8; ++i) {
        rowAcc[i] += __shfl_xor_sync(0xffffffffu, rowAcc[i], 1);
        rowAcc[i] += __shfl_xor_sync(0xffffffffu, rowAcc[i], 2);
    }
    __syncthreads();                       // tiles dead; overlay RED at SM_A
    float* red = (float*)(smem + SM_A);
    if (tq == 0) {
        #pragma unroll
        for (int mf = 0; mf < 4; ++mf)
            #pragma unroll
            for (int h = 0; h < 2; ++h) {
                int row = warpM*64 + mf*16 + g + h*8;
                red[row * 2 + warpN] = rowAcc[mf*2 + h];
            }
    }
    __syncthreads();

    // final value per row + fused loss partial
    {
        int row = rowBase + tid;
        const int outLimit = isX ? nRows : mCols;
        float val = red[tid*2] + red[tid*2 + 1];
        float contrib = 0.f;
        if (row < outLimit) {
            outp[row] = val;
            if (isX) {
                float d = val - Y[row];
                contrib = d * d;
            } else {
                contrib = c2a[row].y * val;    // alpha * predMM
            }
        }
        __syncthreads();
        float* blk = (float*)(smem + SM_A);
        blk[tid] = contrib;
        __syncthreads();
        #pragma unroll
        for (int off = 64; off > 0; off >>= 1) {
            if (tid < off) blk[tid] += blk[tid + off];
            __syncthreads();
        }
        if (tid == 0) partials[blockIdx.x] = blk[0];
    }
}

// ===================== finalize =====================
__global__ void final_kernel(const float* __restrict__ partials,
                             int nBlocksX, int nBlocksTot,
                             const float* __restrict__ penalty_p,
                             float* __restrict__ out_total, int n) {
    int tid = threadIdx.x;
    float s = 0.0f, rg = 0.0f;
    for (int i = tid; i < nBlocksX; i += 256) s += partials[i];
    for (int i = nBlocksX + tid; i < nBlocksTot; i += 256) rg += partials[i];
    __shared__ float sm[256], sm2[256];
    sm[tid] = s; sm2[tid] = rg;
    __syncthreads();
    #pragma unroll
    for (int off = 128; off > 0; off >>= 1) {
        if (tid < off) { sm[tid] += sm[tid + off]; sm2[tid] += sm2[tid + off]; }
        __syncthreads();
    }
    if (tid == 0)
        out_total[0] = sm[0] / (float)n + expf(-penalty_p[0]) * sm2[0];
}

// ===================== launch =====================
extern "C" void kernel_launch(void* const* d_in, const int* in_sizes, int n_in,
                              void* d_out, int out_size) {
    const float* X       = (const float*)d_in[0];
    const float* Y       = (const float*)d_in[1];
    const float* centers = (const float*)d_in[2];
    const float* alpha   = (const float*)d_in[3];
    const float* sigma   = (const float*)d_in[4];
    const float* penalty = (const float*)d_in[5];
    float* out = (float*)d_out;

    const int N = in_sizes[0] / DIMK;
    const int M = in_sizes[2] / DIMK;

    uint8_t* Cb;
    float *predsMM, *partials, *preds_fb;
    float2* c2a;
    cudaGetSymbolAddress((void**)&Cb,       g_Cb);
    cudaGetSymbolAddress((void**)&c2a,      g_c2a);
    cudaGetSymbolAddress((void**)&predsMM,  g_predsMM);
    cudaGetSymbolAddress((void**)&partials, g_partials);
    cudaGetSymbolAddress((void**)&preds_fb, g_preds_fallback);

    float* preds_ptr = preds_fb;
    float* total_ptr = out;
    if (out_size >= N + 1)  { total_ptr = out; preds_ptr = out + 1; }
    else if (out_size == N) { preds_ptr = out; total_ptr = preds_fb; }

    const int nBlocksX = (N + 127) / 128;
    const int nBlocksM = (M + 127) / 128;
    const int nBlocksTot = nBlocksX + nBlocksM;

    cudaFuncSetAttribute(rbf_hmma_kernel,
                         cudaFuncAttributeMaxDynamicSharedMemorySize, SMEM_TOTAL);

    convC_kernel<<<(M + 7) / 8, 256>>>(centers, Cb, c2a, alpha, sigma, M);

    rbf_hmma_kernel<<<nBlocksTot, 128, SMEM_TOTAL>>>(
        X, centers, Cb, c2a, Y, sigma, preds_ptr, predsMM, partials,
        N, nBlocksX, M);

    final_kernel<<<1, 256>>>(partials, nBlocksX, nBlocksTot, penalty, total_ptr, N);
}

// round 9
// speedup vs baseline: 1.5224x; 1.5224x over previous
#include <cuda_runtime.h>
#include <cuda_bf16.h>
#include <cstdint>
#include <math.h>

// ===================== constants =====================
static constexpr int DIMK = 128;

// smem layout (bytes), dynamic
static constexpr int TS      = 272;                 // padded row stride (136 bf16)
static constexpr int TILE_B  = 128 * TS;            // 34816
static constexpr int SM_A    = 0;                   // A tile; overlaid by RED at end
static constexpr int SM_B0   = TILE_B;              // 34816
static constexpr int SM_B1   = 2 * TILE_B;          // 69632
static constexpr int SM_CA   = 3 * TILE_B;          // 104448, 4-slot ring x 1KB (float2[128])
static constexpr int SM_NORM = SM_CA + 4096;        // 108544, 128 floats
static constexpr int SMEM_TOTAL = SM_NORM + 512;    // 109056  (2 CTAs/SM: 218KB < 228KB)

// ===================== scratch (no cudaMalloc) =====================
__device__ __nv_bfloat16 g_Cb[2048 * DIMK];
__device__ float2 g_c2a[2048];          // (-0.5*||c'||^2 , alpha)
__device__ float  g_predsMM[2048];
__device__ float  g_partials[1024];
__device__ float  g_preds_fallback[100352];

// ===================== PTX helpers =====================
__device__ __forceinline__ uint32_t smem_u32(const void* p) {
    uint32_t a;
    asm("{ .reg .u64 t; cvta.to.shared.u64 t, %1; cvt.u32.u64 %0, t; }" : "=r"(a) : "l"(p));
    return a;
}
__device__ __forceinline__ void cpa16(uint32_t dst, const void* src) {
    asm volatile("cp.async.cg.shared.global [%0], [%1], 16;" :: "r"(dst), "l"(src));
}
#define CP_COMMIT() asm volatile("cp.async.commit_group;" ::: "memory")
#define CP_WAIT0()  asm volatile("cp.async.wait_group 0;"  ::: "memory")

__device__ __forceinline__ void ldmx4(uint32_t* r, uint32_t addr) {
    asm volatile("ldmatrix.sync.aligned.m8n8.x4.shared.b16 {%0,%1,%2,%3}, [%4];"
                 : "=r"(r[0]), "=r"(r[1]), "=r"(r[2]), "=r"(r[3]) : "r"(addr));
}
__device__ __forceinline__ void mma16816(float* c, const uint32_t* a,
                                         uint32_t b0, uint32_t b1) {
    asm volatile("mma.sync.aligned.m16n8k16.row.col.f32.bf16.bf16.f32 "
                 "{%0,%1,%2,%3}, {%4,%5,%6,%7}, {%8,%9}, {%0,%1,%2,%3};"
                 : "+f"(c[0]), "+f"(c[1]), "+f"(c[2]), "+f"(c[3])
                 : "r"(a[0]), "r"(a[1]), "r"(a[2]), "r"(a[3]), "r"(b0), "r"(b1));
}
__device__ __forceinline__ float ex2f(float x) {
    float y; asm("ex2.approx.ftz.f32 %0, %1;" : "=f"(y) : "f"(x)); return y;
}
// q = sqrt(log2e)/sigma so that (q a)·(q b) = log2e * (a.b)/sigma^2
__device__ __forceinline__ float qscale(float sg) {
    return sqrtf(1.44269504088896340736f) / sg;
}

// ===================== centers conv: fp32 -> bf16 (scaled), (d, alpha) ======
__global__ void convC_kernel(const float* __restrict__ C,
                             __nv_bfloat16* __restrict__ Cb,
                             float2* __restrict__ c2a,
                             const float* __restrict__ alpha,
                             const float* __restrict__ sigma_p, int m)
{
    int row  = blockIdx.x * 8 + (threadIdx.x >> 5);
    int lane = threadIdx.x & 31;
    if (row >= m) return;
    const float q = qscale(*sigma_p);
    float4 v = ((const float4*)(C + (size_t)row * DIMK))[lane];
    __nv_bfloat162 p0 = __floats2bfloat162_rn(q * v.x, q * v.y);
    __nv_bfloat162 p1 = __floats2bfloat162_rn(q * v.z, q * v.w);
    float r0 = __bfloat162float(p0.x), r1 = __bfloat162float(p0.y);
    float r2 = __bfloat162float(p1.x), r3 = __bfloat162float(p1.y);
    float s = r0*r0 + r1*r1 + r2*r2 + r3*r3;
    #pragma unroll
    for (int o = 16; o > 0; o >>= 1) s += __shfl_xor_sync(0xffffffffu, s, o);
    __nv_bfloat162* dst = (__nv_bfloat162*)(Cb + (size_t)row * DIMK) + lane * 2;
    dst[0] = p0; dst[1] = p1;
    if (lane == 0) c2a[row] = make_float2(-0.5f * s, alpha[row]);
}

// ===================== B-tile async loader (bf16 128x128, 128 threads) =====
__device__ __forceinline__ void load_tile_async(uint32_t smBase,
                                                const __nv_bfloat16* __restrict__ src,
                                                int tid)
{
    #pragma unroll
    for (int it = 0; it < 16; ++it) {
        int i   = tid + it * 128;
        int row = i >> 4;
        int kb  = i & 15;
        cpa16(smBase + row * TS + kb * 16, (const char*)src + row * 256 + kb * 16);
    }
}

// ===================== fused RBF matvec + loss partials =====================
// Blocks [0, nBlocksX): rows of X -> preds, partial = sum (pred-y)^2
// rest: rows of centers -> predsMM,  partial = sum alpha*predMM
__global__ void __launch_bounds__(128, 2)
rbf_hmma_kernel(const float* __restrict__ Xf, const float* __restrict__ Cf,
                const __nv_bfloat16* __restrict__ Cb,
                const float2* __restrict__ c2a,
                const float* __restrict__ Y,
                const float* __restrict__ sigma_p,
                float* __restrict__ preds, float* __restrict__ predsMM,
                float* __restrict__ partials,
                int nRows, int nBlocksX, int mCols)
{
    extern __shared__ char smem[];
    const uint32_t sb = smem_u32(smem);
    const int tid   = threadIdx.x;
    const int lane  = tid & 31;
    const int wid   = tid >> 5;
    const int warpM = wid & 1;          // 2 warps over M (64 rows each)
    const int warpN = wid >> 1;         // 2 warps over N (64 cols each)
    const int g     = lane >> 2;
    const int tq    = lane & 3;

    const bool isX = ((int)blockIdx.x < nBlocksX);
    const float* Asrc  = isX ? Xf : Cf;
    const int   srcN   = isX ? nRows : mCols;
    float* outp        = isX ? preds : predsMM;
    const int rowBase  = (isX ? blockIdx.x : blockIdx.x - nBlocksX) * 128;

    const float q = qscale(*sigma_p);

    // ---- prologue: start async C tile 0 + CA slot 0 ----
    load_tile_async(sb + SM_B0, Cb, tid);
    if (tid < 64) cpa16(sb + SM_CA + tid * 16, (const char*)c2a + tid * 16);
    CP_COMMIT();

    // ---- load A tile fp32 -> scaled bf16 smem (coalesced) ----
    #pragma unroll
    for (int i = 0; i < 32; ++i) {
        int idx = tid + i * 128;            // 4096 float4 chunks
        int r = idx >> 5, c4 = idx & 31;
        int gr = rowBase + r; if (gr >= srcN) gr = srcN - 1;
        float4 v = ((const float4*)(Asrc + (size_t)gr * DIMK))[c4];
        __nv_bfloat162 p0 = __floats2bfloat162_rn(q * v.x, q * v.y);
        __nv_bfloat162 p1 = __floats2bfloat162_rn(q * v.z, q * v.w);
        uint2 w;
        w.x = *(const uint32_t*)&p0; w.y = *(const uint32_t*)&p1;
        *(uint2*)(smem + SM_A + r * TS + c4 * 8) = w;
    }
    __syncthreads();

    // ---- row norms from ROUNDED scaled bf16 (1 thread/row) ----
    {
        float nrm = 0.f;
        #pragma unroll
        for (int j = 0; j < 16; ++j) {
            uint4 v = *(const uint4*)(smem + SM_A + tid * TS + j * 16);
            const uint32_t* u = (const uint32_t*)&v;
            #pragma unroll
            for (int qq = 0; qq < 4; ++qq) {
                float2 f = __bfloat1622float2(*(const __nv_bfloat162*)&u[qq]);
                nrm = fmaf(f.x, f.x, nrm);
                nrm = fmaf(f.y, f.y, nrm);
            }
        }
        ((float*)(smem + SM_NORM))[tid] = -0.5f * nrm;
    }
    __syncthreads();

    // caR[mf*2+h] = -0.5*||row||^2 for rows warpM*64 + mf*16 + g + h*8
    float caR[8];
    {
        const float* nm = (const float*)(smem + SM_NORM);
        #pragma unroll
        for (int mf = 0; mf < 4; ++mf)
            #pragma unroll
            for (int h = 0; h < 2; ++h)
                caR[mf*2 + h] = nm[warpM*64 + mf*16 + g + h*8];
    }

    // ---- A fragments persist in registers across ALL tiles ----
    const int ti = lane >> 3, rr = lane & 7;
    uint32_t aF[4][8][4];               // [mf][ks][4] = 128 regs
    #pragma unroll
    for (int mf = 0; mf < 4; ++mf) {
        uint32_t base = sb + SM_A + (warpM*64 + mf*16 + (ti & 1)*8 + rr) * TS
                        + (ti >> 1) * 16;
        #pragma unroll
        for (int ks = 0; ks < 8; ++ks) ldmx4(aF[mf][ks], base + ks * 32);
    }

    // B ldmatrix offsets (4 slices of 16 cols)
    uint32_t bOff[4];
    #pragma unroll
    for (int p = 0; p < 4; ++p)
        bOff[p] = (uint32_t)((warpN*64 + p*16 + (ti >> 1)*8 + rr) * TS + (ti & 1) * 16);

    float acc[2][4][2][4];          // ping-pong accumulator sets (64 regs)
    float rowAcc[8] = {0.f,0.f,0.f,0.f,0.f,0.f,0.f,0.f};
    const int nT = mCols >> 7;      // 16
    const char* caPrev = smem + SM_CA + (size_t)warpN * 512;   // updated per tile
    CP_WAIT0();
    __syncthreads();

    for (int t = 0; t < nT; ++t) {
        if (t + 1 < nT) {
            load_tile_async(sb + (((t + 1) & 1) ? SM_B1 : SM_B0),
                            Cb + (size_t)(t + 1) * 128 * DIMK, tid);
            if (tid < 64)
                cpa16(sb + SM_CA + ((t + 1) & 3) * 1024 + tid * 16,
                      (const char*)(c2a + (size_t)(t + 1) * 128) + tid * 16);
            CP_COMMIT();
        }
        const uint32_t bB = sb + ((t & 1) ? SM_B1 : SM_B0);
        const char*   caP = smem + SM_CA + (t & 3) * 1024 + (size_t)warpN * 512;

        // 4 slices of 16 cols; epilogue of slice p-1 interleaved per k-step
        #pragma unroll
        for (int p = 0; p < 4; ++p) {
            float*       aC = &acc[p & 1][0][0][0];
            const bool  doE = (p > 0) || (t > 0);
            const int    pe = (p == 0) ? 3 : p - 1;          // prev slice index
            const char* caE = (p == 0) ? caPrev : caP;       // prev slice CA base

            #pragma unroll
            for (int z = 0; z < 32; ++z) aC[z] = 0.f;

            uint32_t rb[2][4];
            ldmx4(rb[0], bB + bOff[p]);
            float4 ccReg;
            #pragma unroll
            for (int ks = 0; ks < 8; ++ks) {
                if (ks < 7) ldmx4(rb[(ks + 1) & 1], bB + bOff[p] + (ks + 1) * 32);
                const uint32_t* b = rb[ks & 1];
                #pragma unroll
                for (int mf = 0; mf < 4; ++mf) {
                    mma16816(acc[p & 1][mf][0], aF[mf][ks], b[0], b[1]);
                    mma16816(acc[p & 1][mf][1], aF[mf][ks], b[2], b[3]);
                }
                // interleaved epilogue chunk of previous slice
                if (doE) {
                    const int emf = ks & 3, enl = ks >> 2;
                    if (emf == 0)
                        ccReg = *(const float4*)(caE + ((pe*2 + enl)*8 + tq*2) * 8);
                    const float* a = acc[(p & 1) ^ 1][emf][enl];
                    float e0 = a[0] + (caR[emf*2]     + ccReg.x);
                    float e1 = a[1] + (caR[emf*2]     + ccReg.z);
                    float e2 = a[2] + (caR[emf*2 + 1] + ccReg.x);
                    float e3 = a[3] + (caR[emf*2 + 1] + ccReg.z);
                    rowAcc[emf*2]     = fmaf(ex2f(e0), ccReg.y, rowAcc[emf*2]);
                    rowAcc[emf*2]     = fmaf(ex2f(e1), ccReg.w, rowAcc[emf*2]);
                    rowAcc[emf*2 + 1] = fmaf(ex2f(e2), ccReg.y, rowAcc[emf*2 + 1]);
                    rowAcc[emf*2 + 1] = fmaf(ex2f(e3), ccReg.w, rowAcc[emf*2 + 1]);
                }
            }
        }
        caPrev = caP;
        CP_WAIT0();
        __syncthreads();
    }

    // flush epilogue for the final slice (p=3 of tile nT-1, lives in acc[1])
    {
        const char* caE = smem + SM_CA + (size_t)((nT - 1) & 3) * 1024
                        + (size_t)warpN * 512;
        #pragma unroll
        for (int ch = 0; ch < 8; ++ch) {
            const int emf = ch & 3, enl = ch >> 2;
            float4 cc = *(const float4*)(caE + ((3*2 + enl)*8 + tq*2) * 8);
            const float* a = acc[1][emf][enl];
            float e0 = a[0] + (caR[emf*2]     + cc.x);
            float e1 = a[1] + (caR[emf*2]     + cc.z);
            float e2 = a[2] + (caR[emf*2 + 1] + cc.x);
            float e3 = a[3] + (caR[emf*2 + 1] + cc.z);
            rowAcc[emf*2]     = fmaf(ex2f(e0), cc.y, rowAcc[emf*2]);
            rowAcc[emf*2]     = fmaf(ex2f(e1), cc.w, rowAcc[emf*2]);
            rowAcc[emf*2 + 1] = fmaf(ex2f(e2), cc.y, rowAcc[emf*2 + 1]);
            rowAcc[emf*2 + 1] = fmaf(ex2f(e3), cc.w, rowAcc[emf*2 + 1]);
        }
    }

    // quad reduce (4 threads share each row), then cross-warpN via smem
    #pragma unroll
    for (int i = 0; i < 8; ++i) {
        rowAcc[i] += __shfl_xor_sync(0xffffffffu, rowAcc[i], 1);
        rowAcc[i] += __shfl_xor_sync(0xffffffffu, rowAcc[i], 2);
    }
    __syncthreads();                       // tiles dead; overlay RED at SM_A
    float* red = (float*)(smem + SM_A);
    if (tq == 0) {
        #pragma unroll
        for (int mf = 0; mf < 4; ++mf)
            #pragma unroll
            for (int h = 0; h < 2; ++h) {
                int row = warpM*64 + mf*16 + g + h*8;
                red[row * 2 + warpN] = rowAcc[mf*2 + h];
            }
    }
    __syncthreads();

    // final value per row + fused loss partial
    {
        int row = rowBase + tid;
        const int outLimit = isX ? nRows : mCols;
        float val = red[tid*2] + red[tid*2 + 1];
        float contrib = 0.f;
        if (row < outLimit) {
            outp[row] = val;
            if (isX) {
                float d = val - Y[row];
                contrib = d * d;
            } else {
                contrib = c2a[row].y * val;    // alpha * predMM
            }
        }
        __syncthreads();
        float* blk = (float*)(smem + SM_A);
        blk[tid] = contrib;
        __syncthreads();
        #pragma unroll
        for (int off = 64; off > 0; off >>= 1) {
            if (tid < off) blk[tid] += blk[tid + off];
            __syncthreads();
        }
        if (tid == 0) partials[blockIdx.x] = blk[0];
    }
}

// ===================== finalize =====================
__global__ void final_kernel(const float* __restrict__ partials,
                             int nBlocksX, int nBlocksTot,
                             const float* __restrict__ penalty_p,
                             float* __restrict__ out_total, int n) {
    int tid = threadIdx.x;
    float s = 0.0f, rg = 0.0f;
    for (int i = tid; i < nBlocksX; i += 256) s += partials[i];
    for (int i = nBlocksX + tid; i < nBlocksTot; i += 256) rg += partials[i];
    __shared__ float sm[256], sm2[256];
    sm[tid] = s; sm2[tid] = rg;
    __syncthreads();
    #pragma unroll
    for (int off = 128; off > 0; off >>= 1) {
        if (tid < off) { sm[tid] += sm[tid + off]; sm2[tid] += sm2[tid + off]; }
        __syncthreads();
    }
    if (tid == 0)
        out_total[0] = sm[0] / (float)n + expf(-penalty_p[0]) * sm2[0];
}

// ===================== launch =====================
extern "C" void kernel_launch(void* const* d_in, const int* in_sizes, int n_in,
                              void* d_out, int out_size) {
    const float* X       = (const float*)d_in[0];
    const float* Y       = (const float*)d_in[1];
    const float* centers = (const float*)d_in[2];
    const float* alpha   = (const float*)d_in[3];
    const float* sigma   = (const float*)d_in[4];
    const float* penalty = (const float*)d_in[5];
    float* out = (float*)d_out;

    const int N = in_sizes[0] / DIMK;
    const int M = in_sizes[2] / DIMK;

    __nv_bfloat16* Cb;
    float *predsMM, *partials, *preds_fb;
    float2* c2a;
    cudaGetSymbolAddress((void**)&Cb,       g_Cb);
    cudaGetSymbolAddress((void**)&c2a,      g_c2a);
    cudaGetSymbolAddress((void**)&predsMM,  g_predsMM);
    cudaGetSymbolAddress((void**)&partials, g_partials);
    cudaGetSymbolAddress((void**)&preds_fb, g_preds_fallback);

    float* preds_ptr = preds_fb;
    float* total_ptr = out;
    if (out_size >= N + 1)  { total_ptr = out; preds_ptr = out + 1; }
    else if (out_size == N) { preds_ptr = out; total_ptr = preds_fb; }

    const int nBlocksX = (N + 127) / 128;
    const int nBlocksM = (M + 127) / 128;
    const int nBlocksTot = nBlocksX + nBlocksM;

    cudaFuncSetAttribute(rbf_hmma_kernel,
                         cudaFuncAttributeMaxDynamicSharedMemorySize, SMEM_TOTAL);

    convC_kernel<<<(M + 7) / 8, 256>>>(centers, Cb, c2a, alpha, sigma, M);

    rbf_hmma_kernel<<<nBlocksTot, 128, SMEM_TOTAL>>>(
        X, centers, Cb, c2a, Y, sigma, preds_ptr, predsMM, partials,
        N, nBlocksX, M);

    final_kernel<<<1, 256>>>(partials, nBlocksX, nBlocksTot, penalty, total_ptr, N);
}